// round 2
// baseline (speedup 1.0000x reference)
#include <cuda_runtime.h>

#define B_    16
#define C_    256
#define H_    56
#define W_    56
#define HW_   3136
#define MID_  64
#define OC2_  144   // KK * GROUPS = 9 * 16
#define GROUPS_ 16
#define GS_   16

// scratch for per-pixel kernels: [B][144][HW]  (~28.9 MB, static device alloc)
__device__ float g_weight[B_ * OC2_ * HW_];

// ---------------------------------------------------------------------------
// Kernel 1: fused  conv1(1x1) + BN + ReLU + conv2(1x1) + bias
// One block = 64 pixels of one batch image. 256 threads.
// Stage 1: t[64][64px] = w1[64x256] * x[256][64px]   (smem-tiled, 4x4 microtile)
// Stage 2: weight[144][64px] = w2[144x64] * t + b2   (3x4 microtile, t in smem)
// ---------------------------------------------------------------------------
__global__ __launch_bounds__(256) void fused_conv_kernel(
    const float* __restrict__ x,
    const float* __restrict__ w1,
    const float* __restrict__ bn_gamma,
    const float* __restrict__ bn_beta,
    const float* __restrict__ bn_mean,
    const float* __restrict__ bn_var,
    const float* __restrict__ w2,
    const float* __restrict__ b2)
{
    __shared__ float As[32][64];    // w1 chunk: [k][o]
    __shared__ float Bs[32][64];    // x  chunk: [k][p]
    __shared__ float Ts[64][80];    // t (mid x pixels), stride 80 -> conflict-free

    const int tid = threadIdx.x;
    const int blk = blockIdx.x;
    const int b   = blk / (HW_ / 64);
    const int hw0 = (blk % (HW_ / 64)) * 64;

    const float* xb = x + (size_t)b * C_ * HW_ + hw0;

    const int tx = tid & 15;   // pixel group 0..15
    const int ty = tid >> 4;   // mid group   0..15

    float acc[4][4];
    #pragma unroll
    for (int i = 0; i < 4; i++)
        #pragma unroll
        for (int j = 0; j < 4; j++) acc[i][j] = 0.f;

    for (int kt = 0; kt < C_; kt += 32) {
        // load w1 tile: 64 o x 32 k  (2048 elems)
        #pragma unroll
        for (int i = 0; i < 8; i++) {
            int idx = tid + i * 256;
            int o = idx >> 5, kc = idx & 31;
            As[kc][o] = w1[o * C_ + kt + kc];
        }
        // load x tile: 32 k x 64 p
        #pragma unroll
        for (int i = 0; i < 8; i++) {
            int idx = tid + i * 256;
            int kc = idx >> 6, p = idx & 63;
            Bs[kc][p] = xb[(size_t)(kt + kc) * HW_ + p];
        }
        __syncthreads();

        #pragma unroll
        for (int kc = 0; kc < 32; kc++) {
            float a0 = As[kc][ty], a1 = As[kc][ty + 16],
                  a2 = As[kc][ty + 32], a3 = As[kc][ty + 48];
            float p0 = Bs[kc][tx], p1 = Bs[kc][tx + 16],
                  p2 = Bs[kc][tx + 32], p3 = Bs[kc][tx + 48];
            acc[0][0] += a0 * p0; acc[0][1] += a0 * p1; acc[0][2] += a0 * p2; acc[0][3] += a0 * p3;
            acc[1][0] += a1 * p0; acc[1][1] += a1 * p1; acc[1][2] += a1 * p2; acc[1][3] += a1 * p3;
            acc[2][0] += a2 * p0; acc[2][1] += a2 * p1; acc[2][2] += a2 * p2; acc[2][3] += a2 * p3;
            acc[3][0] += a3 * p0; acc[3][1] += a3 * p1; acc[3][2] += a3 * p2; acc[3][3] += a3 * p3;
        }
        __syncthreads();
    }

    // BN (eval) + ReLU epilogue -> Ts
    #pragma unroll
    for (int i = 0; i < 4; i++) {
        int o = ty + 16 * i;
        float s  = bn_gamma[o] * rsqrtf(bn_var[o] + 1e-5f);
        float sh = bn_beta[o] - bn_mean[o] * s;
        #pragma unroll
        for (int j = 0; j < 4; j++) {
            float t = fmaxf(acc[i][j] * s + sh, 0.f);
            Ts[o][tx + 16 * j] = t;
        }
    }
    __syncthreads();

    // Stage 2: weight[o2][p] = sum_k w2[o2][k] * Ts[k][p] + b2[o2]
    float* wout = g_weight + (size_t)b * OC2_ * HW_ + hw0;

    #pragma unroll
    for (int rr = 0; rr < 3; rr++) {
        int o2a = ty + 16 * (rr * 3 + 0);
        int o2b = ty + 16 * (rr * 3 + 1);
        int o2c = ty + 16 * (rr * 3 + 2);
        float ac0[4], ac1[4], ac2[4];
        #pragma unroll
        for (int j = 0; j < 4; j++) { ac0[j] = 0.f; ac1[j] = 0.f; ac2[j] = 0.f; }

        #pragma unroll 8
        for (int k = 0; k < MID_; k++) {
            float t0 = Ts[k][tx], t1 = Ts[k][tx + 16],
                  t2 = Ts[k][tx + 32], t3 = Ts[k][tx + 48];
            float wa = __ldg(&w2[o2a * MID_ + k]);
            float wb = __ldg(&w2[o2b * MID_ + k]);
            float wc = __ldg(&w2[o2c * MID_ + k]);
            ac0[0] += wa * t0; ac0[1] += wa * t1; ac0[2] += wa * t2; ac0[3] += wa * t3;
            ac1[0] += wb * t0; ac1[1] += wb * t1; ac1[2] += wb * t2; ac1[3] += wb * t3;
            ac2[0] += wc * t0; ac2[1] += wc * t1; ac2[2] += wc * t2; ac2[3] += wc * t3;
        }
        float bb0 = __ldg(&b2[o2a]), bb1 = __ldg(&b2[o2b]), bb2 = __ldg(&b2[o2c]);
        #pragma unroll
        for (int j = 0; j < 4; j++) {
            wout[(size_t)o2a * HW_ + tx + 16 * j] = ac0[j] + bb0;
            wout[(size_t)o2b * HW_ + tx + 16 * j] = ac1[j] + bb1;
            wout[(size_t)o2c * HW_ + tx + 16 * j] = ac2[j] + bb2;
        }
    }
}

// ---------------------------------------------------------------------------
// Kernel 2: involution.  One block = (b, group g, output row y).
// smem: 9x56 per-pixel kernel weights + 16ch x 3rows x 58cols x halo.
// out[b, g*16+gs, y, x] = sum_kk ws[kk][x] * x[b, g*16+gs, y+di-1, x+dj-1]
// ---------------------------------------------------------------------------
__global__ __launch_bounds__(256) void involution_kernel(
    const float* __restrict__ x,
    float* __restrict__ out)
{
    __shared__ float ws[9][56];
    __shared__ float xs[16][3][60];

    const int y = blockIdx.x;
    const int g = blockIdx.y;
    const int b = blockIdx.z;
    const int tid = threadIdx.x;

    // load per-pixel kernels for this (b, g, y)
    const float* wsrc = g_weight + ((size_t)b * OC2_ + g * 9) * HW_ + y * W_;
    for (int idx = tid; idx < 9 * 56; idx += 256) {
        int kk = idx / 56, xc = idx - kk * 56;
        ws[kk][xc] = wsrc[(size_t)kk * HW_ + xc];
    }

    // load x halo: 16 channels x 3 rows x 58 cols (zero-padded)
    const float* xsrc = x + ((size_t)b * C_ + g * GS_) * HW_;
    for (int idx = tid; idx < 16 * 3 * 58; idx += 256) {
        int c = idx / 174;
        int rem = idx - c * 174;
        int r = rem / 58;
        int xx = rem - r * 58;
        int yy = y + r - 1;
        int gx = xx - 1;
        float v = 0.f;
        if (yy >= 0 && yy < H_ && gx >= 0 && gx < W_)
            v = xsrc[(size_t)c * HW_ + yy * W_ + gx];
        xs[c][r][xx] = v;
    }
    __syncthreads();

    float* outp = out + ((size_t)b * C_ + g * GS_) * HW_ + y * W_;
    for (int idx = tid; idx < GS_ * 56; idx += 256) {
        int gs = idx / 56, xc = idx - gs * 56;
        float acc = 0.f;
        #pragma unroll
        for (int kk = 0; kk < 9; kk++) {
            int di = kk / 3, dj = kk - di * 3;
            acc += ws[kk][xc] * xs[gs][di][xc + dj];
        }
        outp[(size_t)gs * HW_ + xc] = acc;
    }
}

extern "C" void kernel_launch(void* const* d_in, const int* in_sizes, int n_in,
                              void* d_out, int out_size)
{
    const float* x        = (const float*)d_in[0];
    const float* w1       = (const float*)d_in[1];
    const float* bn_gamma = (const float*)d_in[2];
    const float* bn_beta  = (const float*)d_in[3];
    const float* bn_mean  = (const float*)d_in[4];
    const float* bn_var   = (const float*)d_in[5];
    const float* w2       = (const float*)d_in[6];
    const float* b2       = (const float*)d_in[7];
    float* out = (float*)d_out;

    fused_conv_kernel<<<B_ * (HW_ / 64), 256>>>(
        x, w1, bn_gamma, bn_beta, bn_mean, bn_var, w2, b2);

    involution_kernel<<<dim3(H_, GROUPS_, B_), 256>>>(x, out);
}

// round 4
// speedup vs baseline: 1.3852x; 1.3852x over previous
#include <cuda_runtime.h>

#define B_    16
#define C_    256
#define H_    56
#define W_    56
#define HW_   3136
#define MID_  64
#define OC2_  144   // KK * GROUPS = 9 * 16

// scratch for per-pixel kernels: [B][144][HW]  (~28.9 MB, static device alloc)
__device__ float g_weight[B_ * OC2_ * HW_];

// ---------------------------------------------------------------------------
// Kernel 1: fused  conv1(1x1) + BN + ReLU + conv2(1x1) + bias
// 128 threads, one block = 64 pixels of one image.
// Stage 1: t[64][64px]  = w1[64x256] * x[256][64px]   (8mid x 4px microtile)
// Stage 2: w [144][64px]= w2[144x64] * t + b2         (6o2 x 4px, 3 passes)
// ---------------------------------------------------------------------------
__global__ __launch_bounds__(128) void fused_conv_kernel(
    const float* __restrict__ x,
    const float* __restrict__ w1,
    const float* __restrict__ bn_gamma,
    const float* __restrict__ bn_beta,
    const float* __restrict__ bn_mean,
    const float* __restrict__ bn_var,
    const float* __restrict__ w2,
    const float* __restrict__ b2)
{
    __shared__ float As[32][64];    // w1 chunk transposed: [k][o]      8 KB
    __shared__ float Bs[32][64];    // x  chunk:            [k][p]      8 KB
    __shared__ float Ts[64][64];    // relu(bn(t)):         [mid][p]   16 KB
    __shared__ float W2s[64][64];   // w2 slice transposed: [k][slot]  16 KB
                                    //                        total  = 48 KB

    const int tid = threadIdx.x;
    const int blk = blockIdx.x;
    const int b   = blk / 49;
    const int hw0 = (blk % 49) * 64;

    const float* xb = x + (size_t)b * C_ * HW_ + hw0;

    const int px0 = (tid & 15) * 4;   // 4 consecutive pixels
    const int ms  = tid >> 4;         // mid-slot 0..7 (8 consecutive mids)

    float acc[8][4];
    #pragma unroll
    for (int i = 0; i < 8; i++)
        #pragma unroll
        for (int j = 0; j < 4; j++) acc[i][j] = 0.f;

    const int o_a = tid & 63;       // for As loads
    const int kh  = tid >> 6;       // 0..1

    for (int kt = 0; kt < C_; kt += 32) {
        // load w1 tile transposed: As[k][o]
        #pragma unroll
        for (int q = 0; q < 4; q++) {
            float4 v = *(const float4*)&w1[o_a * C_ + kt + kh * 16 + q * 4];
            As[kh * 16 + q * 4 + 0][o_a] = v.x;
            As[kh * 16 + q * 4 + 1][o_a] = v.y;
            As[kh * 16 + q * 4 + 2][o_a] = v.z;
            As[kh * 16 + q * 4 + 3][o_a] = v.w;
        }
        // load x tile: Bs[k][p], float4
        #pragma unroll
        for (int j = 0; j < 4; j++) {
            int f4i = tid + 128 * j;
            int kc  = f4i >> 4;
            int p4  = (f4i & 15) * 4;
            *(float4*)&Bs[kc][p4] =
                *(const float4*)&xb[(size_t)(kt + kc) * HW_ + p4];
        }
        __syncthreads();

        #pragma unroll
        for (int kc = 0; kc < 32; kc++) {
            float4 p  = *(const float4*)&Bs[kc][px0];
            float4 a0 = *(const float4*)&As[kc][ms * 8];
            float4 a1 = *(const float4*)&As[kc][ms * 8 + 4];
            float av[8] = {a0.x, a0.y, a0.z, a0.w, a1.x, a1.y, a1.z, a1.w};
            float pv[4] = {p.x, p.y, p.z, p.w};
            #pragma unroll
            for (int i = 0; i < 8; i++)
                #pragma unroll
                for (int j = 0; j < 4; j++)
                    acc[i][j] = fmaf(av[i], pv[j], acc[i][j]);
        }
        __syncthreads();
    }

    // BN (eval) + ReLU epilogue -> Ts
    #pragma unroll
    for (int i = 0; i < 8; i++) {
        int o = ms * 8 + i;
        float s  = bn_gamma[o] * rsqrtf(bn_var[o] + 1e-5f);
        float sh = bn_beta[o] - bn_mean[o] * s;
        float4 t;
        t.x = fmaxf(fmaf(acc[i][0], s, sh), 0.f);
        t.y = fmaxf(fmaf(acc[i][1], s, sh), 0.f);
        t.z = fmaxf(fmaf(acc[i][2], s, sh), 0.f);
        t.w = fmaxf(fmaf(acc[i][3], s, sh), 0.f);
        *(float4*)&Ts[o][px0] = t;
    }
    __syncthreads();

    // Stage 2: three passes over 48 output rows each
    float* wout = g_weight + (size_t)b * OC2_ * HW_ + hw0;

    for (int rr = 0; rr < 3; rr++) {
        // load w2 slice transposed into W2s[k][ms*8 + ii]
        // lr = local row 0..47 -> o2 = (lr/6)*18 + rr*6 + lr%6, slot = (lr/6)*8 + lr%6
        #pragma unroll
        for (int j = 0; j < 6; j++) {
            int lr = (tid & 15) + 16 * (j % 3);       // 0..47
            int kq = (tid >> 4) + 8 * (j / 3);        // 0..15
            int k4 = kq * 4;
            int msl = lr / 6, ii = lr - msl * 6;
            int o2 = msl * 18 + rr * 6 + ii;
            float4 v = *(const float4*)&w2[o2 * MID_ + k4];
            int lslot = msl * 8 + ii;
            W2s[k4 + 0][lslot] = v.x;
            W2s[k4 + 1][lslot] = v.y;
            W2s[k4 + 2][lslot] = v.z;
            W2s[k4 + 3][lslot] = v.w;
        }
        __syncthreads();

        float acc2[6][4];
        #pragma unroll
        for (int ii = 0; ii < 6; ii++)
            #pragma unroll
            for (int j = 0; j < 4; j++) acc2[ii][j] = 0.f;

        #pragma unroll 16
        for (int k = 0; k < MID_; k++) {
            float4 tp = *(const float4*)&Ts[k][px0];
            float4 wa = *(const float4*)&W2s[k][ms * 8];
            float2 wb = *(const float2*)&W2s[k][ms * 8 + 4];
            float wv[6] = {wa.x, wa.y, wa.z, wa.w, wb.x, wb.y};
            float tv[4] = {tp.x, tp.y, tp.z, tp.w};
            #pragma unroll
            for (int ii = 0; ii < 6; ii++)
                #pragma unroll
                for (int j = 0; j < 4; j++)
                    acc2[ii][j] = fmaf(wv[ii], tv[j], acc2[ii][j]);
        }

        #pragma unroll
        for (int ii = 0; ii < 6; ii++) {
            int o2 = ms * 18 + rr * 6 + ii;
            float bias = b2[o2];
            float4 o4;
            o4.x = acc2[ii][0] + bias;
            o4.y = acc2[ii][1] + bias;
            o4.z = acc2[ii][2] + bias;
            o4.w = acc2[ii][3] + bias;
            *(float4*)&wout[(size_t)o2 * HW_ + px0] = o4;
        }
        __syncthreads();
    }
}

// ---------------------------------------------------------------------------
// Kernel 2: involution. Block = (ytile of 8 rows, group g, b x gs-half).
// 128 threads: r = tid>>4 (row 0..7), slot = tid&15 (x-quad, 14 active).
// Per-thread: 9 kernel weights (x4 cols) in registers, loop 8 channels.
// ---------------------------------------------------------------------------
__global__ __launch_bounds__(128) void involution_kernel(
    const float* __restrict__ x,
    float* __restrict__ out)
{
    __shared__ float xs[10][8][60];   // [row -1..+8][ch][col -1..58]  19.2 KB
    __shared__ float ws[9][8][60];    // [kk][row][col]                17.3 KB

    const int y0  = blockIdx.x * 8;
    const int g   = blockIdx.y;
    const int b   = blockIdx.z >> 1;
    const int gh  = (blockIdx.z & 1) * 8;   // channel half within group
    const int tid = threadIdx.x;
    const int warp = tid >> 5, lane = tid & 31;

    // load x halo: 8 channels x 10 rows x 58 cols (zero-padded edges)
    const float* xsrc = x + ((size_t)(b * C_ + g * 16 + gh)) * HW_;
    for (int ri = warp; ri < 80; ri += 4) {
        int row = ri >> 3, c = ri & 7;
        int gy = y0 + row - 1;
        bool rowok = ((unsigned)gy < (unsigned)H_);
        const float* src = xsrc + (size_t)c * HW_ + gy * W_;
        #pragma unroll
        for (int col = lane; col < 60; col += 32) {
            int gx = col - 1;
            float v = 0.f;
            if (rowok && (unsigned)gx < (unsigned)W_) v = src[gx];
            xs[row][c][col] = v;
        }
    }
    // load per-pixel kernels: 9 kk x 8 rows x 56 cols
    const float* wsrc = g_weight + ((size_t)(b * OC2_ + g * 9)) * HW_ + y0 * W_;
    for (int ri = warp; ri < 72; ri += 4) {
        int kk = ri >> 3, r = ri & 7;
        const float* src = wsrc + (size_t)kk * HW_ + r * W_;
        #pragma unroll
        for (int col = lane; col < 56; col += 32)
            ws[kk][r][col] = src[col];
    }
    __syncthreads();

    const int slot = tid & 15;
    const int r    = tid >> 4;
    if (slot < 14) {
        const int x0 = slot * 4;
        float wv[9][4];
        #pragma unroll
        for (int kk = 0; kk < 9; kk++) {
            float4 t = *(const float4*)&ws[kk][r][x0];
            wv[kk][0] = t.x; wv[kk][1] = t.y; wv[kk][2] = t.z; wv[kk][3] = t.w;
        }
        float* outp = out + ((size_t)(b * C_ + g * 16 + gh)) * HW_
                    + (y0 + r) * W_ + x0;
        #pragma unroll 2
        for (int gs = 0; gs < 8; gs++) {
            float acc[4] = {0.f, 0.f, 0.f, 0.f};
            #pragma unroll
            for (int dr = 0; dr < 3; dr++) {
                const float* xr = &xs[r + dr][gs][x0];
                float4 v4 = *(const float4*)xr;
                float2 v2 = *(const float2*)(xr + 4);
                float xv[6] = {v4.x, v4.y, v4.z, v4.w, v2.x, v2.y};
                #pragma unroll
                for (int dj = 0; dj < 3; dj++)
                    #pragma unroll
                    for (int j = 0; j < 4; j++)
                        acc[j] = fmaf(wv[dr * 3 + dj][j], xv[j + dj], acc[j]);
            }
            float4 o4 = {acc[0], acc[1], acc[2], acc[3]};
            *(float4*)&outp[(size_t)gs * HW_] = o4;
        }
    }
}

extern "C" void kernel_launch(void* const* d_in, const int* in_sizes, int n_in,
                              void* d_out, int out_size)
{
    const float* x        = (const float*)d_in[0];
    const float* w1       = (const float*)d_in[1];
    const float* bn_gamma = (const float*)d_in[2];
    const float* bn_beta  = (const float*)d_in[3];
    const float* bn_mean  = (const float*)d_in[4];
    const float* bn_var   = (const float*)d_in[5];
    const float* w2       = (const float*)d_in[6];
    const float* b2       = (const float*)d_in[7];
    float* out = (float*)d_out;

    fused_conv_kernel<<<B_ * 49, 128>>>(
        x, w1, bn_gamma, bn_beta, bn_mean, bn_var, w2, b2);

    involution_kernel<<<dim3(7, 16, 32), 128>>>(x, out);
}

// round 7
// speedup vs baseline: 1.9279x; 1.3918x over previous
#include <cuda_runtime.h>

#define B_    16
#define C_    256
#define H_    56
#define W_    56
#define HW_   3136
#define MID_  64
#define OC2_  144   // KK * GROUPS = 9 * 16

// scratch for per-pixel kernels: [B][144][HW]  (~28.9 MB, static device alloc)
__device__ float g_weight[B_ * OC2_ * HW_];

// ---- packed f32x2 helpers ------------------------------------------------
typedef unsigned long long ull;

__device__ __forceinline__ ull pack2(float lo, float hi) {
    ull r;
    asm("mov.b64 %0, {%1, %2};" : "=l"(r) : "f"(lo), "f"(hi));
    return r;
}
__device__ __forceinline__ void unpack2(ull v, float& lo, float& hi) {
    asm("mov.b64 {%0, %1}, %2;" : "=f"(lo), "=f"(hi) : "l"(v));
}
__device__ __forceinline__ void ffma2(ull& d, ull a, ull b) {
    asm("fma.rn.f32x2 %0, %1, %2, %0;" : "+l"(d) : "l"(a), "l"(b));
}

union F4U2 { float4 f; ull u[2]; };
union F2U1 { float2 f; ull u; };

// ---------------------------------------------------------------------------
// Kernel 1: fused  conv1(1x1) + BN + ReLU + conv2(1x1) + bias
// 128 threads, one block = 64 pixels of one image.
// Stage 1: t[64][64px]  = w1[64x256] * x[256][64px]   (8mid x 4px, FFMA2 pairs)
// Stage 2: w [144][64px]= w2[144x64] * t + b2         (6o2 x 4px, 3 passes)
// ---------------------------------------------------------------------------
__global__ __launch_bounds__(128) void fused_conv_kernel(
    const float* __restrict__ x,
    const float* __restrict__ w1,
    const float* __restrict__ bn_gamma,
    const float* __restrict__ bn_beta,
    const float* __restrict__ bn_mean,
    const float* __restrict__ bn_var,
    const float* __restrict__ w2,
    const float* __restrict__ b2)
{
    __shared__ float As[32][64];    // w1 chunk transposed: [k][o]      8 KB
    __shared__ float Bs[32][64];    // x  chunk:            [k][p]      8 KB
    __shared__ float Ts[64][64];    // relu(bn(t)):         [mid][p]   16 KB
    __shared__ float W2s[64][64];   // w2 slice transposed: [k][slot]  16 KB

    const int tid = threadIdx.x;
    const int blk = blockIdx.x;
    const int b   = blk / 49;
    const int hw0 = (blk % 49) * 64;

    const float* xb = x + (size_t)b * C_ * HW_ + hw0;

    const int px0 = (tid & 15) * 4;   // 4 consecutive pixels
    const int ms  = tid >> 4;         // mid-slot 0..7 (8 consecutive mids)

    // packed accumulators: accp[i2][j] holds mids (ms*8+2*i2, ms*8+2*i2+1), pixel j
    ull accp[4][4];
    #pragma unroll
    for (int i = 0; i < 4; i++)
        #pragma unroll
        for (int j = 0; j < 4; j++) accp[i][j] = 0ull;

    const int o_a = tid & 63;       // for As loads
    const int kh  = tid >> 6;       // 0..1

    for (int kt = 0; kt < C_; kt += 32) {
        // load w1 tile transposed: As[k][o]
        #pragma unroll
        for (int q = 0; q < 4; q++) {
            float4 v = *(const float4*)&w1[o_a * C_ + kt + kh * 16 + q * 4];
            As[kh * 16 + q * 4 + 0][o_a] = v.x;
            As[kh * 16 + q * 4 + 1][o_a] = v.y;
            As[kh * 16 + q * 4 + 2][o_a] = v.z;
            As[kh * 16 + q * 4 + 3][o_a] = v.w;
        }
        // load x tile: Bs[k][p], float4
        #pragma unroll
        for (int j = 0; j < 4; j++) {
            int f4i = tid + 128 * j;
            int kc  = f4i >> 4;
            int p4  = (f4i & 15) * 4;
            *(float4*)&Bs[kc][p4] =
                *(const float4*)&xb[(size_t)(kt + kc) * HW_ + p4];
        }
        __syncthreads();

        #pragma unroll
        for (int kc = 0; kc < 32; kc++) {
            F4U2 A0, A1;
            A0.f = *(const float4*)&As[kc][ms * 8];
            A1.f = *(const float4*)&As[kc][ms * 8 + 4];
            float4 p = *(const float4*)&Bs[kc][px0];
            ull pd[4];
            pd[0] = pack2(p.x, p.x);
            pd[1] = pack2(p.y, p.y);
            pd[2] = pack2(p.z, p.z);
            pd[3] = pack2(p.w, p.w);
            ull ap[4] = {A0.u[0], A0.u[1], A1.u[0], A1.u[1]};
            #pragma unroll
            for (int i = 0; i < 4; i++)
                #pragma unroll
                for (int j = 0; j < 4; j++)
                    ffma2(accp[i][j], ap[i], pd[j]);
        }
        __syncthreads();
    }

    // unpack + BN (eval) + ReLU epilogue -> Ts
    #pragma unroll
    for (int i2 = 0; i2 < 4; i2++) {
        int o0 = ms * 8 + 2 * i2;
        float s0  = bn_gamma[o0] * rsqrtf(bn_var[o0] + 1e-5f);
        float sh0 = bn_beta[o0] - bn_mean[o0] * s0;
        float s1  = bn_gamma[o0 + 1] * rsqrtf(bn_var[o0 + 1] + 1e-5f);
        float sh1 = bn_beta[o0 + 1] - bn_mean[o0 + 1] * s1;
        float t0[4], t1[4];
        #pragma unroll
        for (int j = 0; j < 4; j++) {
            float lo, hi;
            unpack2(accp[i2][j], lo, hi);
            t0[j] = fmaxf(fmaf(lo, s0, sh0), 0.f);
            t1[j] = fmaxf(fmaf(hi, s1, sh1), 0.f);
        }
        *(float4*)&Ts[o0][px0]     = make_float4(t0[0], t0[1], t0[2], t0[3]);
        *(float4*)&Ts[o0 + 1][px0] = make_float4(t1[0], t1[1], t1[2], t1[3]);
    }
    __syncthreads();

    // Stage 2: three passes over 48 output rows each
    float* wout = g_weight + (size_t)b * OC2_ * HW_ + hw0;

    for (int rr = 0; rr < 3; rr++) {
        // load w2 slice transposed into W2s[k][ms*8 + ii]
        #pragma unroll
        for (int j = 0; j < 6; j++) {
            int lr = (tid & 15) + 16 * (j % 3);       // 0..47
            int kq = (tid >> 4) + 8 * (j / 3);        // 0..15
            int k4 = kq * 4;
            int msl = lr / 6, ii = lr - msl * 6;
            int o2 = msl * 18 + rr * 6 + ii;
            float4 v = *(const float4*)&w2[o2 * MID_ + k4];
            int lslot = msl * 8 + ii;
            W2s[k4 + 0][lslot] = v.x;
            W2s[k4 + 1][lslot] = v.y;
            W2s[k4 + 2][lslot] = v.z;
            W2s[k4 + 3][lslot] = v.w;
        }
        __syncthreads();

        // packed accumulators: accq[q][j] holds o2 rows (2q, 2q+1) of this thread's 6
        ull accq[3][4];
        #pragma unroll
        for (int q = 0; q < 3; q++)
            #pragma unroll
            for (int j = 0; j < 4; j++) accq[q][j] = 0ull;

        #pragma unroll 16
        for (int k = 0; k < MID_; k++) {
            F4U2 WA; F2U1 WB;
            WA.f = *(const float4*)&W2s[k][ms * 8];
            WB.f = *(const float2*)&W2s[k][ms * 8 + 4];
            float4 tp = *(const float4*)&Ts[k][px0];
            ull td[4];
            td[0] = pack2(tp.x, tp.x);
            td[1] = pack2(tp.y, tp.y);
            td[2] = pack2(tp.z, tp.z);
            td[3] = pack2(tp.w, tp.w);
            ull wp[3] = {WA.u[0], WA.u[1], WB.u};
            #pragma unroll
            for (int q = 0; q < 3; q++)
                #pragma unroll
                for (int j = 0; j < 4; j++)
                    ffma2(accq[q][j], wp[q], td[j]);
        }

        #pragma unroll
        for (int q = 0; q < 3; q++) {
            int iiA = 2 * q, iiB = 2 * q + 1;
            int o2A = ms * 18 + rr * 6 + iiA;
            int o2B = ms * 18 + rr * 6 + iiB;
            float bA = b2[o2A], bB = b2[o2B];
            float oA[4], oB[4];
            #pragma unroll
            for (int j = 0; j < 4; j++) {
                float lo, hi;
                unpack2(accq[q][j], lo, hi);
                oA[j] = lo + bA;
                oB[j] = hi + bB;
            }
            *(float4*)&wout[(size_t)o2A * HW_ + px0] = make_float4(oA[0], oA[1], oA[2], oA[3]);
            *(float4*)&wout[(size_t)o2B * HW_ + px0] = make_float4(oB[0], oB[1], oB[2], oB[3]);
        }
        __syncthreads();
    }
}

// ---------------------------------------------------------------------------
// Kernel 2: involution. Block = (4-row tile, group g, b). 256 threads:
// gs = tid>>4 (channel 0..15), slot = tid&15 (col quad, 14 active).
// Each thread: 4 rows x 4 cols of one channel. Weights LDS'd just-in-time
// (low registers -> smem-limited occupancy: 7 blocks/SM, 56 warps).
// ---------------------------------------------------------------------------
__global__ __launch_bounds__(256) void involution_kernel(
    const float* __restrict__ x,
    float* __restrict__ out)
{
    __shared__ float ws[9][224];      // [kk][r*56+col], 4 rows contiguous   8.1 KB
    __shared__ float xs[6][16][60];   // [y0-1..y0+4][ch][col -1..58]       23.0 KB

    const int y0  = blockIdx.x * 4;
    const int g   = blockIdx.y;
    const int b   = blockIdx.z;
    const int tid = threadIdx.x;
    const int warp = tid >> 5, lane = tid & 31;

    // x halo: 6 rows x 16 channels x 58 cols (zero-padded edges)
    const float* xsrc = x + ((size_t)(b * C_ + g * 16)) * HW_;
    for (int seg = warp; seg < 96; seg += 8) {
        int row = seg >> 4, c = seg & 15;
        int gy = y0 + row - 1;
        bool rowok = ((unsigned)gy < (unsigned)H_);
        const float* src = xsrc + (size_t)c * HW_ + gy * W_;
        #pragma unroll
        for (int q = 0; q < 2; q++) {
            int col = lane + q * 32;
            if (col < 60) {
                int gx = col - 1;
                float v = 0.f;
                if (rowok && (unsigned)gx < (unsigned)W_) v = src[gx];
                xs[row][c][col] = v;
            }
        }
    }
    // per-pixel kernels: 9 kk, rows y0..y0+3 are 224 contiguous floats each
    const float* wsrc = g_weight + ((size_t)(b * OC2_ + g * 9)) * HW_ + y0 * W_;
    for (int kk = warp; kk < 9; kk += 8) {
        #pragma unroll
        for (int q = 0; q < 7; q++) {
            int col = lane + q * 32;
            ws[kk][col] = wsrc[(size_t)kk * HW_ + col];
        }
    }
    __syncthreads();

    const int gs   = tid >> 4;
    const int slot = tid & 15;
    if (slot >= 14) return;
    const int x0 = slot * 4;

    float* outp = out + ((size_t)(b * C_ + g * 16 + gs)) * HW_ + y0 * W_ + x0;

    #pragma unroll
    for (int r = 0; r < 4; r++) {
        float a0 = 0.f, a1 = 0.f, a2 = 0.f, a3 = 0.f;
        const int wb = r * 56 + x0;
        #pragma unroll
        for (int dr = 0; dr < 3; dr++) {
            const float* xr = &xs[r + dr][gs][x0];
            float4 v4 = *(const float4*)xr;
            float2 v2 = *(const float2*)(xr + 4);

            float4 w0 = *(const float4*)&ws[dr * 3 + 0][wb];
            a0 = fmaf(w0.x, v4.x, a0);
            a1 = fmaf(w0.y, v4.y, a1);
            a2 = fmaf(w0.z, v4.z, a2);
            a3 = fmaf(w0.w, v4.w, a3);

            float4 w1_ = *(const float4*)&ws[dr * 3 + 1][wb];
            a0 = fmaf(w1_.x, v4.y, a0);
            a1 = fmaf(w1_.y, v4.z, a1);
            a2 = fmaf(w1_.z, v4.w, a2);
            a3 = fmaf(w1_.w, v2.x, a3);

            float4 w2_ = *(const float4*)&ws[dr * 3 + 2][wb];
            a0 = fmaf(w2_.x, v4.z, a0);
            a1 = fmaf(w2_.y, v4.w, a1);
            a2 = fmaf(w2_.z, v2.x, a2);
            a3 = fmaf(w2_.w, v2.y, a3);
        }
        *(float4*)&outp[r * W_] = make_float4(a0, a1, a2, a3);
    }
}

extern "C" void kernel_launch(void* const* d_in, const int* in_sizes, int n_in,
                              void* d_out, int out_size)
{
    const float* x        = (const float*)d_in[0];
    const float* w1       = (const float*)d_in[1];
    const float* bn_gamma = (const float*)d_in[2];
    const float* bn_beta  = (const float*)d_in[3];
    const float* bn_mean  = (const float*)d_in[4];
    const float* bn_var   = (const float*)d_in[5];
    const float* w2       = (const float*)d_in[6];
    const float* b2       = (const float*)d_in[7];
    float* out = (float*)d_out;

    fused_conv_kernel<<<B_ * 49, 128>>>(
        x, w1, bn_gamma, bn_beta, bn_mean, bn_var, w2, b2);

    involution_kernel<<<dim3(14, 16, 16), 256>>>(x, out);
}